// round 5
// baseline (speedup 1.0000x reference)
#include <cuda_runtime.h>
#include <cuda_bf16.h>

#define GRIDN   32
#define NPLANE  1089        // 33*33
#define NVOL    35937       // 33^3
#define T_ROWS  48
#define NT      128
#define PPB     64          // points per block (two threads per point)

// ---------------------------------------------------------------------------
__global__ void zero_out_kernel(float4* __restrict__ out, int n4) {
    int i = blockIdx.x * blockDim.x + threadIdx.x;
    if (i < n4) out[i] = make_float4(0.f, 0.f, 0.f, 0.f);
}

__device__ __forceinline__ float safeden(float x) {
    return (fabsf(x) > 1e-12f) ? x : 1e-12f;
}

// Non-contractible dot: bitwise-identical inputs -> bitwise-identical result,
// exact zeros for zero vectors.  Replicates XLA (non-FMA) classification math.
__device__ __forceinline__ float dot_rn(float ax, float ay, float az,
                                        float bx, float by, float bz) {
    return __fadd_rn(__fadd_rn(__fmul_rn(ax, bx), __fmul_rn(ay, by)),
                     __fmul_rn(az, bz));
}

// ---------------------------------------------------------------------------
// Point-triangle squared distance.
// Classification (d1..d6, va/vb/vc, e43/e56): EXACT (non-contracted) so
// duplicate-vertex degenerate triangles resolve identically to the reference.
// Candidate distances: algebraic form  dist^2 = base - num/den  with a single
// division; selection follows the reference where-stack overwrite order:
// interior -> BC -> AC -> C -> AB -> B -> A  (A wins).
// Garbage guard: legit r = num/den lies in [0, base]; out-of-range (only from
// near-degenerate noise) is replaced by base (|p-a|^2, a valid upper bound,
// discarded by the min just like the reference's huge garbage values).
// ---------------------------------------------------------------------------
__device__ __forceinline__ float tri_dist_sq(float4 A, float4 B, float4 C) {
    float abx = A.x - B.x, aby = A.y - B.y, abz = A.z - B.z;
    float acx = A.x - C.x, acy = A.y - C.y, acz = A.z - C.z;

    float d1 = dot_rn(abx, aby, abz, A.x, A.y, A.z);
    float d2 = dot_rn(acx, acy, acz, A.x, A.y, A.z);
    float d3 = dot_rn(abx, aby, abz, B.x, B.y, B.z);
    float d4 = dot_rn(acx, acy, acz, B.x, B.y, B.z);
    float d5 = dot_rn(abx, aby, abz, C.x, C.y, C.z);
    float d6 = dot_rn(acx, acy, acz, C.x, C.y, C.z);

    float va = __fsub_rn(__fmul_rn(d3, d6), __fmul_rn(d5, d4));
    float vb = __fsub_rn(__fmul_rn(d5, d2), __fmul_rn(d1, d6));
    float vc = __fsub_rn(__fmul_rn(d1, d4), __fmul_rn(d3, d2));
    float e43 = __fsub_rn(d4, d3);
    float e56 = __fsub_rn(d5, d6);

    // interior (default)
    float base = A.w;
    float num  = vb * d1 + vc * d2;
    float den  = va + vb + vc;
    // edge BC
    if ((va <= 0.f) && (e43 >= 0.f) && (e56 >= 0.f)) { base = B.w; num = e43 * e43; den = e43 + e56; }
    // edge AC
    if ((vb <= 0.f) && (d2 >= 0.f) && (d6 <= 0.f))   { base = A.w; num = d2 * d2;   den = d2 - d6;   }
    // vertex C   (num=0 -> division result 0 regardless of den)
    if ((d6 >= 0.f) && (d5 <= d6))                   { base = C.w; num = 0.f; }
    // edge AB
    if ((vc <= 0.f) && (d1 >= 0.f) && (d3 <= 0.f))   { base = A.w; num = d1 * d1;   den = d1 - d3;   }
    // vertex B
    if ((d3 >= 0.f) && (d4 <= d3))                   { base = B.w; num = 0.f; }
    // vertex A
    if ((d1 <= 0.f) && (d2 <= 0.f))                  { base = A.w; num = 0.f; }

    float r = __fdividef(num, safeden(den));
    float d = fmaxf(base - r, 0.f);
    // garbage guard (near-degenerate noise only): r must be in [0, base]
    if (!((r >= 0.f) && (base - r >= -1e-4f))) d = base;
    return d;
}

// ---------------------------------------------------------------------------
// Main kernel: 64 points per block, 2 threads per point (24 tri rows each).
// ---------------------------------------------------------------------------
__global__ void __launch_bounds__(NT)
pt_dist_kernel(const float* __restrict__ offset,
               const float* __restrict__ points,
               const int*   __restrict__ tri_table,
               float*       __restrict__ out,
               int n_pts)
{
    __shared__ int4   tri_s4[T_ROWS * 3];      // 12 ints (9 used) per row
    __shared__ float4 su[12 * PPB];

    int tid = threadIdx.x;
    // stage tri_table, padded to 12/row, premultiplied by PPB
    for (int k = tid; k < T_ROWS * 12; k += NT) {
        int r = k / 12, c = k - r * 12;
        int v = (c < 9) ? tri_table[r * 9 + c] * PPB : 0;
        ((int*)tri_s4)[k] = v;
    }

    int pt   = tid & (PPB - 1);
    int half = tid >> 6;                       // 0: rows 0..23, 1: rows 24..47
    int i    = blockIdx.x * PPB + pt;
    bool valid = (i < n_pts);
    int il = valid ? i : (n_pts - 1);

    float px = points[3 * il + 0];
    float py = points[3 * il + 1];
    float pz = points[3 * il + 2];

    int cx = min(max((int)floorf(px), 0), GRIDN - 1);
    int cy = min(max((int)floorf(py), 0), GRIDN - 1);
    int cz = min(max((int)floorf(pz), 0), GRIDN - 1);
    float lx = px - (float)cx;
    float ly = py - (float)cy;
    float lz = pz - (float)cz;

    if (half == 0) {
        int cb = cx * NPLANE + cy * 33 + cz;
        const float* o0 = offset;
        const float* o1 = offset + NVOL;
        const float* o2 = offset + 2 * NVOL;

        float t0  = o0[cb];
        float t1  = o1[cb + NPLANE];
        float t2  = o0[cb + 33];
        float t3  = o1[cb];
        float t4  = o0[cb + 1];
        float t5  = o1[cb + NPLANE + 1];
        float t6  = o0[cb + 33 + 1];
        float t7  = o1[cb + 1];
        float t8  = o2[cb];
        float t9  = o2[cb + NPLANE];
        float t10 = o2[cb + NPLANE + 33];
        float t11 = o2[cb + 33];

        #define STORE_U(e, ux, uy, uz) do {                   \
            float _x = (ux), _y = (uy), _z = (uz);            \
            float _w = _x * _x + _y * _y + _z * _z;           \
            su[(e) * PPB + pt] = make_float4(_x, _y, _z, _w); \
        } while (0)

        STORE_U(0,  lx - t0,  ly,       lz      );
        STORE_U(1,  lx - 1.f, ly - t1,  lz      );
        STORE_U(2,  lx - t2,  ly - 1.f, lz      );
        STORE_U(3,  lx,       ly - t3,  lz      );
        STORE_U(4,  lx - t4,  ly,       lz - 1.f);
        STORE_U(5,  lx - 1.f, ly - t5,  lz - 1.f);
        STORE_U(6,  lx - t6,  ly - 1.f, lz - 1.f);
        STORE_U(7,  lx,       ly - t7,  lz - 1.f);
        STORE_U(8,  lx,       ly,       lz - t8 );
        STORE_U(9,  lx - 1.f, ly,       lz - t9 );
        STORE_U(10, lx - 1.f, ly - 1.f, lz - t10);
        STORE_U(11, lx,       ly - 1.f, lz - t11);
        #undef STORE_U
    }
    __syncthreads();

    float* outc = out + (size_t)(((cx * GRIDN) + cy) * GRIDN + cz) * T_ROWS;

    int t0r = half * (T_ROWS / 2);
    #pragma unroll 1
    for (int t = t0r; t < t0r + T_ROWS / 2; t++) {
        int4 r0 = tri_s4[t * 3 + 0];
        int4 r1 = tri_s4[t * 3 + 1];
        int4 r2 = tri_s4[t * 3 + 2];

        float4 A0 = su[r0.x + pt];
        float4 B0 = su[r0.y + pt];
        float4 C0 = su[r0.z + pt];
        float m = tri_dist_sq(A0, B0, C0);

        float4 A1 = su[r0.w + pt];
        float4 B1 = su[r1.x + pt];
        float4 C1 = su[r1.y + pt];
        m = fminf(m, tri_dist_sq(A1, B1, C1));

        float4 A2 = su[r1.z + pt];
        float4 B2 = su[r1.w + pt];
        float4 C2 = su[r2.x + pt];
        m = fminf(m, tri_dist_sq(A2, B2, C2));

        if (valid) atomicAdd(outc + t, m);
    }
}

// ---------------------------------------------------------------------------
extern "C" void kernel_launch(void* const* d_in, const int* in_sizes, int n_in,
                              void* d_out, int out_size) {
    const float* offset    = (const float*)d_in[0];   // (3,33,33,33) fp32
    const float* points    = (const float*)d_in[1];   // (131072,3)   fp32
    const int*   tri_table = (const int*)  d_in[2];   // (48,3,3)     int32
    float* out = (float*)d_out;                       // (32768,48)   fp32

    int n_pts = in_sizes[1] / 3;

    int n4 = out_size / 4;
    zero_out_kernel<<<(n4 + 255) / 256, 256>>>((float4*)out, n4);

    int blocks = (n_pts + PPB - 1) / PPB;
    pt_dist_kernel<<<blocks, NT>>>(offset, points, tri_table, out, n_pts);
}

// round 6
// speedup vs baseline: 1.8372x; 1.8372x over previous
#include <cuda_runtime.h>
#include <cuda_bf16.h>

#define GRIDN   32
#define NPLANE  1089        // 33*33
#define NVOL    35937       // 33^3
#define T_ROWS  48
#define NSUB    144         // 48 rows * 3 sub-triangles
#define NT      128
#define PPB     128         // points per block (one thread per point)

// ---------------------------------------------------------------------------
__global__ void zero_out_kernel(float4* __restrict__ out, int n4) {
    int i = blockIdx.x * blockDim.x + threadIdx.x;
    if (i < n4) out[i] = make_float4(0.f, 0.f, 0.f, 0.f);
}

__device__ __forceinline__ float safeden(float x) {
    return (fabsf(x) > 1e-12f) ? x : 1e-12f;
}

// Packed symmetric pair index for i<=j in [0,12): 0..77
__device__ __forceinline__ int pidx(int i, int j) {
    if (i > j) { int t = i; i = j; j = t; }
    return i * 12 - ((i * (i + 1)) >> 1) + j;
}

// ---------------------------------------------------------------------------
// Point-triangle squared distance from 6 Gram entries.
// d-values are differences of Gram entries -> duplicate-vertex triangles get
// EXACT zeros (same stored value subtracted from itself), reproducing the
// reference's degenerate resolution.  Cross terms va/vb/vc non-contracted.
// Selection follows the reference where-stack overwrite order:
// interior -> BC -> AC -> C -> AB -> B -> A  (A wins).
// dist^2 = base - num/den (single division) + garbage guard for
// near-degenerate noise (legit r is always in [0, base]).
// ---------------------------------------------------------------------------
__device__ __forceinline__ float tri_dist_g(float g_aa, float g_ab, float g_ac,
                                            float g_bb, float g_bc, float g_cc) {
    float d1 = __fsub_rn(g_aa, g_ab);   // dot(ab, ap)
    float d2 = __fsub_rn(g_aa, g_ac);   // dot(ac, ap)
    float d3 = __fsub_rn(g_ab, g_bb);   // dot(ab, bp)
    float d4 = __fsub_rn(g_ab, g_bc);   // dot(ac, bp)
    float d5 = __fsub_rn(g_ac, g_bc);   // dot(ab, cp)
    float d6 = __fsub_rn(g_ac, g_cc);   // dot(ac, cp)

    float va = __fsub_rn(__fmul_rn(d3, d6), __fmul_rn(d5, d4));
    float vb = __fsub_rn(__fmul_rn(d5, d2), __fmul_rn(d1, d6));
    float vc = __fsub_rn(__fmul_rn(d1, d4), __fmul_rn(d3, d2));
    float e43 = __fsub_rn(d4, d3);
    float e56 = __fsub_rn(d5, d6);

    // interior (default)
    float base = g_aa;
    float num  = vb * d1 + vc * d2;
    float den  = va + vb + vc;
    // edge BC
    if ((va <= 0.f) && (e43 >= 0.f) && (e56 >= 0.f)) { base = g_bb; num = e43 * e43; den = e43 + e56; }
    // edge AC
    if ((vb <= 0.f) && (d2 >= 0.f) && (d6 <= 0.f))   { base = g_aa; num = d2 * d2;   den = d2 - d6;   }
    // vertex C (num=0 -> r=0 regardless of den)
    if ((d6 >= 0.f) && (d5 <= d6))                   { base = g_cc; num = 0.f; }
    // edge AB
    if ((vc <= 0.f) && (d1 >= 0.f) && (d3 <= 0.f))   { base = g_aa; num = d1 * d1;   den = d1 - d3;   }
    // vertex B
    if ((d3 >= 0.f) && (d4 <= d3))                   { base = g_bb; num = 0.f; }
    // vertex A
    if ((d1 <= 0.f) && (d2 <= 0.f))                  { base = g_aa; num = 0.f; }

    float r = __fdividef(num, safeden(den));
    float d = fmaxf(base - r, 0.f);
    if (!((r >= 0.f) && (base - r >= -1e-4f))) d = base;   // garbage guard
    return d;
}

// ---------------------------------------------------------------------------
// Main kernel: one thread per point; per-point 78-entry Gram matrix in smem.
// ---------------------------------------------------------------------------
__global__ void __launch_bounds__(NT)
pt_dist_kernel(const float* __restrict__ offset,
               const float* __restrict__ points,
               const int*   __restrict__ tri_table,
               float*       __restrict__ out,
               int n_pts)
{
    __shared__ float su[78 * PPB];     // Gram entries, [entry][point]
    __shared__ int   off_s[NSUB * 8];  // per sub-tri: 6 Gram offsets (x PPB), padded to 8

    int tid = threadIdx.x;
    // Stage per-sub-triangle Gram offsets (premultiplied by PPB).
    for (int k = tid; k < NSUB; k += NT) {
        int a = tri_table[k * 3 + 0];
        int b = tri_table[k * 3 + 1];
        int c = tri_table[k * 3 + 2];
        off_s[k * 8 + 0] = pidx(a, a) * PPB;
        off_s[k * 8 + 1] = pidx(a, b) * PPB;
        off_s[k * 8 + 2] = pidx(a, c) * PPB;
        off_s[k * 8 + 3] = pidx(b, b) * PPB;
        off_s[k * 8 + 4] = pidx(b, c) * PPB;
        off_s[k * 8 + 5] = pidx(c, c) * PPB;
        off_s[k * 8 + 6] = 0;
        off_s[k * 8 + 7] = 0;
    }

    int i = blockIdx.x * NT + tid;
    bool valid = (i < n_pts);
    int il = valid ? i : (n_pts - 1);

    float px = points[3 * il + 0];
    float py = points[3 * il + 1];
    float pz = points[3 * il + 2];

    int cx = min(max((int)floorf(px), 0), GRIDN - 1);
    int cy = min(max((int)floorf(py), 0), GRIDN - 1);
    int cz = min(max((int)floorf(pz), 0), GRIDN - 1);
    float lx = px - (float)cx;
    float ly = py - (float)cy;
    float lz = pz - (float)cz;

    int cb = cx * NPLANE + cy * 33 + cz;
    const float* o0 = offset;
    const float* o1 = offset + NVOL;
    const float* o2 = offset + 2 * NVOL;

    float t0  = o0[cb];
    float t1  = o1[cb + NPLANE];
    float t2  = o0[cb + 33];
    float t3  = o1[cb];
    float t4  = o0[cb + 1];
    float t5  = o1[cb + NPLANE + 1];
    float t6  = o0[cb + 33 + 1];
    float t7  = o1[cb + 1];
    float t8  = o2[cb];
    float t9  = o2[cb + NPLANE];
    float t10 = o2[cb + NPLANE + 33];
    float t11 = o2[cb + 33];

    // u_e = local - v_e for the 12 edge vertices
    float ux[12], uy[12], uz[12];
    ux[0]  = lx - t0;  uy[0]  = ly;       uz[0]  = lz;
    ux[1]  = lx - 1.f; uy[1]  = ly - t1;  uz[1]  = lz;
    ux[2]  = lx - t2;  uy[2]  = ly - 1.f; uz[2]  = lz;
    ux[3]  = lx;       uy[3]  = ly - t3;  uz[3]  = lz;
    ux[4]  = lx - t4;  uy[4]  = ly;       uz[4]  = lz - 1.f;
    ux[5]  = lx - 1.f; uy[5]  = ly - t5;  uz[5]  = lz - 1.f;
    ux[6]  = lx - t6;  uy[6]  = ly - 1.f; uz[6]  = lz - 1.f;
    ux[7]  = lx;       uy[7]  = ly - t7;  uz[7]  = lz - 1.f;
    ux[8]  = lx;       uy[8]  = ly;       uz[8]  = lz - t8;
    ux[9]  = lx - 1.f; uy[9]  = ly;       uz[9]  = lz - t9;
    ux[10] = lx - 1.f; uy[10] = ly - 1.f; uz[10] = lz - t10;
    ux[11] = lx;       uy[11] = ly - 1.f; uz[11] = lz - t11;

    // 78-entry Gram matrix (contraction OK: equal pairs share one stored value)
    #pragma unroll
    for (int a = 0; a < 12; a++) {
        #pragma unroll
        for (int b = a; b < 12; b++) {
            int p = a * 12 - ((a * (a + 1)) >> 1) + b;   // compile-time after unroll
            su[p * PPB + tid] = ux[a] * ux[b] + uy[a] * uy[b] + uz[a] * uz[b];
        }
    }
    __syncthreads();

    float* outc = out + (size_t)(((cx * GRIDN) + cy) * GRIDN + cz) * T_ROWS;

    #pragma unroll 1
    for (int t = 0; t < T_ROWS; t++) {
        float m = 3.402823e38f;
        #pragma unroll
        for (int s = 0; s < 3; s++) {
            int k = t * 3 + s;
            int4 oA = *(const int4*)&off_s[k * 8];       // (aa, ab, ac, bb)
            int2 oB = *(const int2*)&off_s[k * 8 + 4];   // (bc, cc)
            float g_aa = su[oA.x + tid];
            float g_ab = su[oA.y + tid];
            float g_ac = su[oA.z + tid];
            float g_bb = su[oA.w + tid];
            float g_bc = su[oB.x + tid];
            float g_cc = su[oB.y + tid];
            m = fminf(m, tri_dist_g(g_aa, g_ab, g_ac, g_bb, g_bc, g_cc));
        }
        if (valid) atomicAdd(outc + t, m);
    }
}

// ---------------------------------------------------------------------------
extern "C" void kernel_launch(void* const* d_in, const int* in_sizes, int n_in,
                              void* d_out, int out_size) {
    const float* offset    = (const float*)d_in[0];   // (3,33,33,33) fp32
    const float* points    = (const float*)d_in[1];   // (131072,3)   fp32
    const int*   tri_table = (const int*)  d_in[2];   // (48,3,3)     int32
    float* out = (float*)d_out;                       // (32768,48)   fp32

    int n_pts = in_sizes[1] / 3;

    int n4 = out_size / 4;
    zero_out_kernel<<<(n4 + 255) / 256, 256>>>((float4*)out, n4);

    int blocks = (n_pts + NT - 1) / NT;
    pt_dist_kernel<<<blocks, NT>>>(offset, points, tri_table, out, n_pts);
}